// round 6
// baseline (speedup 1.0000x reference)
#include <cuda_runtime.h>
#include <cuda_bf16.h>

#define NG      1024
#define NCHUNK  4
#define CHUNK   (NG / NCHUNK)          // 256
#define IMG_W   256
#define IMG_H   256
#define NPIX    (IMG_W * IMG_H)
#define NTILE   ((IMG_W / 16) * (IMG_H / 16))   // 256
#define QMAX    18.0f                  // bbox truncation: per-gaussian alpha < op*e^-9

// Per-pixel partial composites, interleaved [pixel][chunk]: (acc,T) pairs.
__device__ float2 g_part[NPIX * NCHUNK];
// Per-tile arrival counters (zero-init at load; combiner resets to 0 each run,
// so CUDA-graph replays remain deterministic).
__device__ int g_cnt[NTILE];

__device__ __forceinline__ float fast_sigmoid(float x) {
    return 1.0f / (1.0f + __expf(-x));
}

__global__ void __launch_bounds__(256) render_kernel(
        const float* __restrict__ means,
        const float* __restrict__ scales,
        const float* __restrict__ thetas,
        const float* __restrict__ opacities,
        float* __restrict__ out) {
    __shared__ float4 sp[CHUNK];       // mx, my, ia2, ib2   (pre-scaled by -0.5*log2e)
    __shared__ float2 sc[CHUNK];       // id2, op
    __shared__ int warp_cnt[8];
    __shared__ int warp_off[8];
    __shared__ int s_total;
    __shared__ int s_last;

    const int tid  = threadIdx.y * 16 + threadIdx.x;
    const int warp = tid >> 5;
    const int lane = tid & 31;
    const float h = 2.0f / 255.0f;

    // ---- In-CTA prep of this chunk's gaussians (one per thread) ----
    const int gi = blockIdx.z * CHUNK + tid;
    float mx = means[2 * gi + 0];
    float my = means[2 * gi + 1];
    {   // tanh via exp: tanh(x) = 1 - 2/(e^{2x}+1)
        float ex = __expf(2.0f * mx);
        mx = 1.0f - 2.0f / (ex + 1.0f);
        float ey = __expf(2.0f * my);
        my = 1.0f - 2.0f / (ey + 1.0f);
    }
    float s0 = __expf(scales[2 * gi + 0]);
    float s1 = __expf(scales[2 * gi + 1]);
    float th = fast_sigmoid(thetas[gi]) * 6.283185307179586f;
    float op = fast_sigmoid(opacities[gi]);

    float si, c;
    __sincosf(th, &si, &c);
    float s02 = s0 * s0, s12 = s1 * s1;
    const float J = 1e-6f;
    float a = c * c * s02 + si * si * s12 + J;   // Sigma_00
    float b = c * si * (s02 - s12);              // Sigma_01
    float d = si * si * s02 + c * c * s12 + J;   // Sigma_11
    float inv = 1.0f / (a * d - b * b);
    const float NEG_HALF_LOG2E = -0.7213475204444817f;   // -0.5 * log2(e)
    float ia2 =  d * inv * NEG_HALF_LOG2E;
    float ib2 = -b * inv * NEG_HALF_LOG2E;
    float id2 =  a * inv * NEG_HALF_LOG2E;
    float rx = sqrtf(QMAX * a);
    float ry = sqrtf(QMAX * d);

    // ---- Tile bbox test + stable (order-preserving) compaction into smem ----
    const float cx   = -1.0f + ((float)(blockIdx.x * 16) + 7.5f) * h;
    const float cy   = -1.0f + ((float)(blockIdx.y * 16) + 7.5f) * h;
    const float half = 7.5f * h;
    bool pass = (fabsf(mx - cx) < rx + half) && (fabsf(my - cy) < ry + half);

    unsigned bal = __ballot_sync(0xffffffffu, pass);
    int pre = __popc(bal & ((1u << lane) - 1u));
    if (lane == 0) warp_cnt[warp] = __popc(bal);
    __syncthreads();
    if (tid == 0) {
        int s = 0;
        #pragma unroll
        for (int w = 0; w < 8; ++w) { warp_off[w] = s; s += warp_cnt[w]; }
        s_total = s;
    }
    __syncthreads();
    if (pass) {
        int slot = warp_off[warp] + pre;
        sp[slot] = make_float4(mx, my, ia2, ib2);
        sc[slot] = make_float2(id2, op);
    }
    __syncthreads();
    const int cnt = s_total;

    // ---- Per-pixel branchless composite over compacted list (order kept) ----
    const int px = blockIdx.x * 16 + threadIdx.x;
    const int py = blockIdx.y * 16 + threadIdx.y;
    const float x = -1.0f + (float)px * h;
    const float y = -1.0f + (float)py * h;

    float acc = 0.0f;
    float T = 1.0f;

    #pragma unroll 4
    for (int i = 0; i < cnt; ++i) {
        float4 p  = sp[i];
        float2 c2 = sc[i];
        float dx = x - p.x;
        float dy = y - p.y;
        float u = fmaf(p.z, dx, p.w * dy);          // -0.5*log2e * (ia*dx + ib*dy)
        float v = fmaf(p.w, dx, c2.x * dy);
        float qh = fmaf(u, dx, v * dy);             // -0.5*log2e * q
        float alpha = c2.y * exp2f(qh);             // single MUFU.EX2
        float aT = alpha * T;
        acc += aT;
        T   -= aT;
    }

    const int pix = py * IMG_W + px;
    g_part[pix * NCHUNK + blockIdx.z] = make_float2(acc, T);

    // ---- Last-arriving chunk-CTA of this tile performs the combine ----
    const int tile = blockIdx.y * (IMG_W / 16) + blockIdx.x;
    __threadfence();            // publish partials before signaling
    __syncthreads();            // all threads' stores + fences done
    if (tid == 0)
        s_last = (atomicAdd(&g_cnt[tile], 1) == NCHUNK - 1);
    __syncthreads();

    if (s_last) {
        __threadfence();        // acquire: see other CTAs' partials
        const float4* g4 = (const float4*)g_part;
        float4 u0 = g4[pix * 2 + 0];   // (acc0,T0,acc1,T1)
        float4 u1 = g4[pix * 2 + 1];   // (acc2,T2,acc3,T3)
        // acc = a0 + T0*(a1 + T1*(a2 + T2*a3))
        float r = fmaf(u0.y, fmaf(u0.w, fmaf(u1.y, u1.z, u1.x), u0.z), u0.x);
        int o = pix * 3;
        out[o + 0] = r;
        out[o + 1] = r;
        out[o + 2] = r;         // BG = 0, all channels equal
        if (tid == 0) g_cnt[tile] = 0;   // reset for next graph replay
    }
}

extern "C" void kernel_launch(void* const* d_in, const int* in_sizes, int n_in,
                              void* d_out, int out_size) {
    const float* means     = (const float*)d_in[0];
    const float* scales    = (const float*)d_in[1];
    const float* thetas    = (const float*)d_in[2];
    const float* opacities = (const float*)d_in[3];
    float* out = (float*)d_out;

    render_kernel<<<dim3(IMG_W / 16, IMG_H / 16, NCHUNK), dim3(16, 16)>>>(
        means, scales, thetas, opacities, out);
}

// round 7
// speedup vs baseline: 1.2314x; 1.2314x over previous
#include <cuda_runtime.h>
#include <cuda_bf16.h>

#define NG      1024
#define NCHUNK  4
#define CHUNK   (NG / NCHUNK)          // 256
#define IMG_W   256
#define IMG_H   256
#define NPIX    (IMG_W * IMG_H)
#define TILE_W  32
#define TILE_H  16
#define NTX     (IMG_W / TILE_W)       // 8
#define NTY     (IMG_H / TILE_H)       // 16
#define NTILE   (NTX * NTY)            // 128
#define QMAX    12.0f                  // bbox truncation: missed alpha <= op*e^-6

// Per-pixel partial composites, interleaved [pixel][chunk]: (acc,T) pairs.
__device__ float2 g_part[NPIX * NCHUNK];
// Per-tile arrival counters (zero at load; combiner resets each run).
__device__ int g_cnt[NTILE];

__device__ __forceinline__ float fast_sigmoid(float x) {
    return 1.0f / (1.0f + __expf(-x));
}
__device__ __forceinline__ float ex2(float x) {
    float y; asm("ex2.approx.ftz.f32 %0, %1;" : "=f"(y) : "f"(x)); return y;
}

__global__ void __launch_bounds__(256) render_kernel(
        const float* __restrict__ means,
        const float* __restrict__ scales,
        const float* __restrict__ thetas,
        const float* __restrict__ opacities,
        float* __restrict__ out) {
    __shared__ float4 s_abcd[CHUNK];   // A, B, C, D  (q-hat polynomial coeffs)
    __shared__ float2 s_ef[CHUNK];     // E, F (+log2 op folded into F)
    __shared__ int warp_cnt[8];
    __shared__ int warp_off[8];
    __shared__ int s_total;
    __shared__ int s_last;

    const int tid  = threadIdx.y * 16 + threadIdx.x;
    const int warp = tid >> 5;
    const int lane = tid & 31;
    const float h = 2.0f / 255.0f;

    // ---- In-CTA prep of this chunk's gaussians (one per thread) ----
    const int gi = blockIdx.z * CHUNK + tid;
    float mx = means[2 * gi + 0];
    float my = means[2 * gi + 1];
    {   // tanh(x) = 1 - 2/(e^{2x}+1)
        float ex = __expf(2.0f * mx);
        mx = 1.0f - 2.0f / (ex + 1.0f);
        float ey = __expf(2.0f * my);
        my = 1.0f - 2.0f / (ey + 1.0f);
    }
    float s0 = __expf(scales[2 * gi + 0]);
    float s1 = __expf(scales[2 * gi + 1]);
    float th = fast_sigmoid(thetas[gi]) * 6.283185307179586f;
    float op = fast_sigmoid(opacities[gi]);

    float si, c;
    __sincosf(th, &si, &c);
    float s02 = s0 * s0, s12 = s1 * s1;
    const float J = 1e-6f;
    float a = c * c * s02 + si * si * s12 + J;   // Sigma_00
    float b = c * si * (s02 - s12);              // Sigma_01
    float d = si * si * s02 + c * c * s12 + J;   // Sigma_11
    float inv = 1.0f / (a * d - b * b);
    const float S = -0.7213475204444817f;        // -0.5 * log2(e)
    float A =  d * inv * S;
    float B = -b * inv * (2.0f * S);
    float C =  a * inv * S;
    float D = -(2.0f * A * mx + B * my);
    float E = -(B * mx + 2.0f * C * my);
    float F = A * mx * mx + B * mx * my + C * my * my + __log2f(op);
    float rx = sqrtf(QMAX * a);
    float ry = sqrtf(QMAX * d);

    // ---- Tile bbox test + stable (order-preserving) compaction into smem ----
    const float cx     = -1.0f + ((float)(blockIdx.x * TILE_W) + 15.5f) * h;
    const float cy     = -1.0f + ((float)(blockIdx.y * TILE_H) + 7.5f) * h;
    const float half_x = 15.5f * h;
    const float half_y = 7.5f * h;
    bool pass = (fabsf(mx - cx) < rx + half_x) && (fabsf(my - cy) < ry + half_y);

    unsigned bal = __ballot_sync(0xffffffffu, pass);
    int pre = __popc(bal & ((1u << lane) - 1u));
    if (lane == 0) warp_cnt[warp] = __popc(bal);
    __syncthreads();
    if (tid == 0) {
        int s = 0;
        #pragma unroll
        for (int w = 0; w < 8; ++w) { warp_off[w] = s; s += warp_cnt[w]; }
        s_total = s;
    }
    __syncthreads();
    if (pass) {
        int slot = warp_off[warp] + pre;
        s_abcd[slot] = make_float4(A, B, C, D);
        s_ef[slot]   = make_float2(E, F);
    }
    __syncthreads();
    const int cnt = s_total;

    // ---- Two pixels per thread (same row, x and x+16 columns) ----
    const int px0 = blockIdx.x * TILE_W + threadIdx.x;
    const int px1 = px0 + 16;
    const int py  = blockIdx.y * TILE_H + threadIdx.y;
    const float x0 = -1.0f + (float)px0 * h;
    const float x1 = x0 + 16.0f * h;
    const float y  = -1.0f + (float)py * h;

    float acc0 = 0.0f, T0 = 1.0f;
    float acc1 = 0.0f, T1 = 1.0f;

    #pragma unroll 2
    for (int i = 0; i < cnt; ++i) {
        float4 p = s_abcd[i];
        float2 e = s_ef[i];
        float t0 = fmaf(p.y, y, p.w);        // B*y + D
        float t1 = fmaf(p.z, y, e.x);        // C*y + E
        float t3 = fmaf(t1, y, e.y);         // (C*y+E)*y + F
        float qa = fmaf(fmaf(p.x, x0, t0), x0, t3);
        float qb = fmaf(fmaf(p.x, x1, t0), x1, t3);
        float aa = ex2(qa);                  // = op * exp(-q/2)
        float ab = ex2(qb);
        float aT0 = aa * T0; acc0 += aT0; T0 -= aT0;
        float aT1 = ab * T1; acc1 += aT1; T1 -= aT1;
    }

    const int pix0 = py * IMG_W + px0;
    const int pix1 = py * IMG_W + px1;
    g_part[pix0 * NCHUNK + blockIdx.z] = make_float2(acc0, T0);
    g_part[pix1 * NCHUNK + blockIdx.z] = make_float2(acc1, T1);

    // ---- Last-arriving chunk-CTA of this tile combines (cheap handshake) ----
    const int tile = blockIdx.y * NTX + blockIdx.x;
    __syncthreads();   // all partial stores issued CTA-wide before tid0 releases
    if (tid == 0) {
        int prev;
        asm volatile("atom.acq_rel.gpu.global.add.s32 %0, [%1], 1;"
                     : "=r"(prev) : "l"(&g_cnt[tile]) : "memory");
        s_last = (prev == NCHUNK - 1);
    }
    __syncthreads();

    if (s_last) {
        const float4* g4 = (const float4*)g_part;
        #pragma unroll
        for (int k = 0; k < 2; ++k) {
            int pix = k ? pix1 : pix0;
            float4 u0 = __ldcg(&g4[pix * 2 + 0]);   // (acc0,T0,acc1,T1)
            float4 u1 = __ldcg(&g4[pix * 2 + 1]);   // (acc2,T2,acc3,T3)
            float r = fmaf(u0.y, fmaf(u0.w, fmaf(u1.y, u1.z, u1.x), u0.z), u0.x);
            int o = pix * 3;
            out[o + 0] = r;
            out[o + 1] = r;
            out[o + 2] = r;     // BG = 0, all channels equal
        }
        if (tid == 0) atomicExch(&g_cnt[tile], 0);   // reset for next replay
    }
}

extern "C" void kernel_launch(void* const* d_in, const int* in_sizes, int n_in,
                              void* d_out, int out_size) {
    const float* means     = (const float*)d_in[0];
    const float* scales    = (const float*)d_in[1];
    const float* thetas    = (const float*)d_in[2];
    const float* opacities = (const float*)d_in[3];
    float* out = (float*)d_out;

    render_kernel<<<dim3(NTX, NTY, NCHUNK), dim3(16, 16)>>>(
        means, scales, thetas, opacities, out);
}

// round 8
// speedup vs baseline: 1.2500x; 1.0151x over previous
#include <cuda_runtime.h>
#include <cuda_bf16.h>

#define NG      1024
#define NCHUNK  8
#define CHUNK   (NG / NCHUNK)          // 128
#define IMG_W   256
#define IMG_H   256
#define NPIX    (IMG_W * IMG_H)
#define TILE_W  32
#define TILE_H  16
#define NTX     (IMG_W / TILE_W)       // 8
#define NTY     (IMG_H / TILE_H)       // 16
#define NTILE   (NTX * NTY)            // 128
#define QMAX    12.0f                  // bbox truncation: missed alpha <= op*e^-6

// Per-pixel partial composites, interleaved [pixel][chunk]: (acc,T) pairs.
__device__ float2 g_part[NPIX * NCHUNK];
// Per-tile arrival counters (zero at load; combiner resets each run).
__device__ int g_cnt[NTILE];

__device__ __forceinline__ float fast_sigmoid(float x) {
    return 1.0f / (1.0f + __expf(-x));
}
__device__ __forceinline__ float ex2(float x) {
    float y; asm("ex2.approx.ftz.f32 %0, %1;" : "=f"(y) : "f"(x)); return y;
}

__global__ void __launch_bounds__(256) render_kernel(
        const float* __restrict__ means,
        const float* __restrict__ scales,
        const float* __restrict__ thetas,
        const float* __restrict__ opacities,
        float* __restrict__ out) {
    __shared__ float4 s_abcd[CHUNK];   // A, B, C, D  (q-hat polynomial coeffs)
    __shared__ float2 s_ef[CHUNK];     // E, F (+log2 op folded into F)
    __shared__ int warp_cnt[4];
    __shared__ int warp_off[4];
    __shared__ int s_total;
    __shared__ int s_last;

    const int tid  = threadIdx.y * 16 + threadIdx.x;
    const int warp = tid >> 5;
    const int lane = tid & 31;
    const float h = 2.0f / 255.0f;

    // ---- In-CTA prep of this chunk's gaussians (tid < CHUNK, one each) ----
    if (tid < CHUNK) {
        const int gi = blockIdx.z * CHUNK + tid;
        float mx = means[2 * gi + 0];
        float my = means[2 * gi + 1];
        {   // tanh(x) = 1 - 2/(e^{2x}+1)
            float ex = __expf(2.0f * mx);
            mx = 1.0f - 2.0f / (ex + 1.0f);
            float ey = __expf(2.0f * my);
            my = 1.0f - 2.0f / (ey + 1.0f);
        }
        float s0 = __expf(scales[2 * gi + 0]);
        float s1 = __expf(scales[2 * gi + 1]);
        float th = fast_sigmoid(thetas[gi]) * 6.283185307179586f;
        float op = fast_sigmoid(opacities[gi]);

        float si, c;
        __sincosf(th, &si, &c);
        float s02 = s0 * s0, s12 = s1 * s1;
        const float J = 1e-6f;
        float a = c * c * s02 + si * si * s12 + J;   // Sigma_00
        float b = c * si * (s02 - s12);              // Sigma_01
        float d = si * si * s02 + c * c * s12 + J;   // Sigma_11
        float inv = 1.0f / (a * d - b * b);
        const float S = -0.7213475204444817f;        // -0.5 * log2(e)
        float A =  d * inv * S;
        float B = -b * inv * (2.0f * S);
        float C =  a * inv * S;
        float D = -(2.0f * A * mx + B * my);
        float E = -(B * mx + 2.0f * C * my);
        float F = A * mx * mx + B * mx * my + C * my * my + __log2f(op);
        float rx = sqrtf(QMAX * a);
        float ry = sqrtf(QMAX * d);

        // ---- Tile bbox test + stable (order-preserving) compaction ----
        const float cx     = -1.0f + ((float)(blockIdx.x * TILE_W) + 15.5f) * h;
        const float cy     = -1.0f + ((float)(blockIdx.y * TILE_H) + 7.5f) * h;
        const float half_x = 15.5f * h;
        const float half_y = 7.5f * h;
        bool pass = (fabsf(mx - cx) < rx + half_x) &&
                    (fabsf(my - cy) < ry + half_y);

        unsigned bal = __ballot_sync(0xffffffffu, pass);
        int pre = __popc(bal & ((1u << lane) - 1u));
        if (lane == 0) warp_cnt[warp] = __popc(bal);
        __syncthreads();
        if (tid == 0) {
            int s = 0;
            #pragma unroll
            for (int w = 0; w < 4; ++w) { warp_off[w] = s; s += warp_cnt[w]; }
            s_total = s;
        }
        __syncthreads();
        if (pass) {
            int slot = warp_off[warp] + pre;
            s_abcd[slot] = make_float4(A, B, C, D);
            s_ef[slot]   = make_float2(E, F);
        }
    } else {
        __syncthreads();
        __syncthreads();
    }
    __syncthreads();
    const int cnt = s_total;

    // ---- Two pixels per thread (same row, x and x+16 columns) ----
    const int px0 = blockIdx.x * TILE_W + threadIdx.x;
    const int px1 = px0 + 16;
    const int py  = blockIdx.y * TILE_H + threadIdx.y;
    const float x0 = -1.0f + (float)px0 * h;
    const float x1 = x0 + 16.0f * h;
    const float y  = -1.0f + (float)py * h;

    float acc0 = 0.0f, T0 = 1.0f;
    float acc1 = 0.0f, T1 = 1.0f;

    #pragma unroll 2
    for (int i = 0; i < cnt; ++i) {
        float4 p = s_abcd[i];
        float2 e = s_ef[i];
        float t0 = fmaf(p.y, y, p.w);        // B*y + D
        float t1 = fmaf(p.z, y, e.x);        // C*y + E
        float t3 = fmaf(t1, y, e.y);         // (C*y+E)*y + F
        float qa = fmaf(fmaf(p.x, x0, t0), x0, t3);
        float qb = fmaf(fmaf(p.x, x1, t0), x1, t3);
        float aa = ex2(qa);                  // = op * exp(-q/2)
        float ab = ex2(qb);
        float aT0 = aa * T0; acc0 += aT0; T0 -= aT0;
        float aT1 = ab * T1; acc1 += aT1; T1 -= aT1;
    }

    const int pix0 = py * IMG_W + px0;
    const int pix1 = py * IMG_W + px1;
    g_part[pix0 * NCHUNK + blockIdx.z] = make_float2(acc0, T0);
    g_part[pix1 * NCHUNK + blockIdx.z] = make_float2(acc1, T1);

    // ---- Last-arriving chunk-CTA of this tile combines (cheap handshake) ----
    const int tile = blockIdx.y * NTX + blockIdx.x;
    __syncthreads();   // all partial stores issued CTA-wide before tid0 releases
    if (tid == 0) {
        int prev;
        asm volatile("atom.acq_rel.gpu.global.add.s32 %0, [%1], 1;"
                     : "=r"(prev) : "l"(&g_cnt[tile]) : "memory");
        s_last = (prev == NCHUNK - 1);
    }
    __syncthreads();

    if (s_last) {
        const float4* g4 = (const float4*)g_part;
        #pragma unroll
        for (int k = 0; k < 2; ++k) {
            int pix = k ? pix1 : pix0;
            float4 u0 = __ldcg(&g4[pix * 4 + 0]);   // chunks 0,1
            float4 u1 = __ldcg(&g4[pix * 4 + 1]);   // chunks 2,3
            float4 u2 = __ldcg(&g4[pix * 4 + 2]);   // chunks 4,5
            float4 u3 = __ldcg(&g4[pix * 4 + 3]);   // chunks 6,7
            // nested front-to-back composition of 8 (acc,T) pairs
            float r = fmaf(u3.y, u3.z, u3.x);       // a6 + T6*a7
            r = fmaf(u2.w, r, u2.z);                // a5 + T5*...
            r = fmaf(u2.y, r, u2.x);
            r = fmaf(u1.w, r, u1.z);
            r = fmaf(u1.y, r, u1.x);
            r = fmaf(u0.w, r, u0.z);
            r = fmaf(u0.y, r, u0.x);
            int o = pix * 3;
            out[o + 0] = r;
            out[o + 1] = r;
            out[o + 2] = r;     // BG = 0, all channels equal
        }
        if (tid == 0) atomicExch(&g_cnt[tile], 0);   // reset for next replay
    }
}

extern "C" void kernel_launch(void* const* d_in, const int* in_sizes, int n_in,
                              void* d_out, int out_size) {
    const float* means     = (const float*)d_in[0];
    const float* scales    = (const float*)d_in[1];
    const float* thetas    = (const float*)d_in[2];
    const float* opacities = (const float*)d_in[3];
    float* out = (float*)d_out;

    render_kernel<<<dim3(NTX, NTY, NCHUNK), dim3(16, 16)>>>(
        means, scales, thetas, opacities, out);
}

// round 9
// speedup vs baseline: 1.2527x; 1.0022x over previous
#include <cuda_runtime.h>
#include <cuda_bf16.h>

#define NG      1024
#define NCHUNK  8
#define CHUNK   (NG / NCHUNK)          // 128
#define IMG_W   256
#define IMG_H   256
#define NPIX    (IMG_W * IMG_H)
#define TILE_W  32
#define TILE_H  16
#define NTX     (IMG_W / TILE_W)       // 8
#define NTY     (IMG_H / TILE_H)       // 16
#define NTILE   (NTX * NTY)            // 128
#define QMAX    12.0f                  // bbox truncation: missed alpha <= op*e^-6

// Per-pixel partial composites, interleaved [pixel][chunk]: (acc,T) pairs.
__device__ float2 g_part[NPIX * NCHUNK];
// Per-tile arrival counters (zero at load; combiner resets each run).
__device__ int g_cnt[NTILE];

__device__ __forceinline__ float fast_sigmoid(float x) {
    return 1.0f / (1.0f + __expf(-x));
}
__device__ __forceinline__ float ex2(float x) {
    float y; asm("ex2.approx.ftz.f32 %0, %1;" : "=f"(y) : "f"(x)); return y;
}

// Block: (32,4) = 128 threads. Thread (tx,ty) owns column x = tile_x + tx and
// 4 rows y = tile_y + ty + 4k, k=0..3  -> 4 independent composite chains.
__global__ void __launch_bounds__(128) render_kernel(
        const float* __restrict__ means,
        const float* __restrict__ scales,
        const float* __restrict__ thetas,
        const float* __restrict__ opacities,
        float* __restrict__ out) {
    __shared__ float4 s_abcd[CHUNK];   // A, B, C, D  (q-hat polynomial coeffs)
    __shared__ float2 s_ef[CHUNK];     // E, F (+log2 op folded into F)
    __shared__ int warp_cnt[4];
    __shared__ int warp_off[4];
    __shared__ int s_total;
    __shared__ int s_last;

    const int tid  = threadIdx.y * 32 + threadIdx.x;
    const int warp = tid >> 5;
    const int lane = tid & 31;
    const float h = 2.0f / 255.0f;

    // ---- In-CTA prep: 128 threads prep the 128 gaussians of this chunk ----
    {
        const int gi = blockIdx.z * CHUNK + tid;
        float mx = means[2 * gi + 0];
        float my = means[2 * gi + 1];
        {   // tanh(x) = 1 - 2/(e^{2x}+1)
            float ex = __expf(2.0f * mx);
            mx = 1.0f - 2.0f / (ex + 1.0f);
            float ey = __expf(2.0f * my);
            my = 1.0f - 2.0f / (ey + 1.0f);
        }
        float s0 = __expf(scales[2 * gi + 0]);
        float s1 = __expf(scales[2 * gi + 1]);
        float th = fast_sigmoid(thetas[gi]) * 6.283185307179586f;
        float op = fast_sigmoid(opacities[gi]);

        float si, c;
        __sincosf(th, &si, &c);
        float s02 = s0 * s0, s12 = s1 * s1;
        const float J = 1e-6f;
        float a = c * c * s02 + si * si * s12 + J;   // Sigma_00
        float b = c * si * (s02 - s12);              // Sigma_01
        float d = si * si * s02 + c * c * s12 + J;   // Sigma_11
        float inv = 1.0f / (a * d - b * b);
        const float S = -0.7213475204444817f;        // -0.5 * log2(e)
        float A =  d * inv * S;
        float B = -b * inv * (2.0f * S);
        float C =  a * inv * S;
        float D = -(2.0f * A * mx + B * my);
        float E = -(B * mx + 2.0f * C * my);
        float F = A * mx * mx + B * mx * my + C * my * my + __log2f(op);
        float rx = sqrtf(QMAX * a);
        float ry = sqrtf(QMAX * d);

        // ---- Tile bbox test + stable (order-preserving) compaction ----
        const float cx     = -1.0f + ((float)(blockIdx.x * TILE_W) + 15.5f) * h;
        const float cy     = -1.0f + ((float)(blockIdx.y * TILE_H) + 7.5f) * h;
        const float half_x = 15.5f * h;
        const float half_y = 7.5f * h;
        bool pass = (fabsf(mx - cx) < rx + half_x) &&
                    (fabsf(my - cy) < ry + half_y);

        unsigned bal = __ballot_sync(0xffffffffu, pass);
        int pre = __popc(bal & ((1u << lane) - 1u));
        if (lane == 0) warp_cnt[warp] = __popc(bal);
        __syncthreads();
        if (tid == 0) {
            int s = 0;
            #pragma unroll
            for (int w = 0; w < 4; ++w) { warp_off[w] = s; s += warp_cnt[w]; }
            s_total = s;
        }
        __syncthreads();
        if (pass) {
            int slot = warp_off[warp] + pre;
            s_abcd[slot] = make_float4(A, B, C, D);
            s_ef[slot]   = make_float2(E, F);
        }
    }
    __syncthreads();
    const int cnt = s_total;

    // ---- Four pixels per thread: one column, rows ty + 4k ----
    const int px  = blockIdx.x * TILE_W + threadIdx.x;
    const int py0 = blockIdx.y * TILE_H + threadIdx.y;    // +0,4,8,12
    const float x  = -1.0f + (float)px * h;
    const float y0 = -1.0f + (float)py0 * h;
    const float y1 = y0 + 4.0f * h;
    const float y2 = y0 + 8.0f * h;
    const float y3 = y0 + 12.0f * h;

    float acc0 = 0.0f, T0 = 1.0f;
    float acc1 = 0.0f, T1 = 1.0f;
    float acc2 = 0.0f, T2 = 1.0f;
    float acc3 = 0.0f, T3 = 1.0f;

    #pragma unroll 2
    for (int i = 0; i < cnt; ++i) {
        float4 p = s_abcd[i];
        float2 e = s_ef[i];
        float hx = fmaf(p.y, x, e.x);                    // B*x + E
        float gx = fmaf(fmaf(p.x, x, p.w), x, e.y);      // (A*x + D)*x + F
        float q0 = fmaf(fmaf(p.z, y0, hx), y0, gx);      // (C*y + hx)*y + gx
        float q1 = fmaf(fmaf(p.z, y1, hx), y1, gx);
        float q2 = fmaf(fmaf(p.z, y2, hx), y2, gx);
        float q3 = fmaf(fmaf(p.z, y3, hx), y3, gx);
        float a0 = ex2(q0);                              // = op * exp(-q/2)
        float a1 = ex2(q1);
        float a2 = ex2(q2);
        float a3 = ex2(q3);
        float t0 = a0 * T0; acc0 += t0; T0 -= t0;
        float t1 = a1 * T1; acc1 += t1; T1 -= t1;
        float t2 = a2 * T2; acc2 += t2; T2 -= t2;
        float t3 = a3 * T3; acc3 += t3; T3 -= t3;
    }

    const int z = blockIdx.z;
    const int pixb = py0 * IMG_W + px;
    g_part[(pixb            ) * NCHUNK + z] = make_float2(acc0, T0);
    g_part[(pixb +  4 * IMG_W) * NCHUNK + z] = make_float2(acc1, T1);
    g_part[(pixb +  8 * IMG_W) * NCHUNK + z] = make_float2(acc2, T2);
    g_part[(pixb + 12 * IMG_W) * NCHUNK + z] = make_float2(acc3, T3);

    // ---- Last-arriving chunk-CTA of this tile combines (cheap handshake) ----
    const int tile = blockIdx.y * NTX + blockIdx.x;
    __syncthreads();   // all partial stores issued CTA-wide before tid0 releases
    if (tid == 0) {
        int prev;
        asm volatile("atom.acq_rel.gpu.global.add.s32 %0, [%1], 1;"
                     : "=r"(prev) : "l"(&g_cnt[tile]) : "memory");
        s_last = (prev == NCHUNK - 1);
    }
    __syncthreads();

    if (s_last) {
        const float4* g4 = (const float4*)g_part;
        #pragma unroll
        for (int k = 0; k < 4; ++k) {
            int pix = pixb + 4 * k * IMG_W;
            float4 u0 = __ldcg(&g4[pix * 4 + 0]);   // chunks 0,1
            float4 u1 = __ldcg(&g4[pix * 4 + 1]);   // chunks 2,3
            float4 u2 = __ldcg(&g4[pix * 4 + 2]);   // chunks 4,5
            float4 u3 = __ldcg(&g4[pix * 4 + 3]);   // chunks 6,7
            float r = fmaf(u3.y, u3.z, u3.x);       // a6 + T6*a7
            r = fmaf(u2.w, r, u2.z);
            r = fmaf(u2.y, r, u2.x);
            r = fmaf(u1.w, r, u1.z);
            r = fmaf(u1.y, r, u1.x);
            r = fmaf(u0.w, r, u0.z);
            r = fmaf(u0.y, r, u0.x);
            int o = pix * 3;
            out[o + 0] = r;
            out[o + 1] = r;
            out[o + 2] = r;     // BG = 0, all channels equal
        }
        if (tid == 0) atomicExch(&g_cnt[tile], 0);   // reset for next replay
    }
}

extern "C" void kernel_launch(void* const* d_in, const int* in_sizes, int n_in,
                              void* d_out, int out_size) {
    const float* means     = (const float*)d_in[0];
    const float* scales    = (const float*)d_in[1];
    const float* thetas    = (const float*)d_in[2];
    const float* opacities = (const float*)d_in[3];
    float* out = (float*)d_out;

    render_kernel<<<dim3(NTX, NTY, NCHUNK), dim3(32, 4)>>>(
        means, scales, thetas, opacities, out);
}